// round 17
// baseline (speedup 1.0000x reference)
#include <cuda_runtime.h>
#include <stdint.h>

// Lukasiewicz t-norm feature expansion — persistent CTAs, double-buffered
// TMA bulk stores.
//   out[:, 0:16)    = x
//   out[:, 16:136)  = max(x[i]+x[j] - 1, 0)       i<j    (120)
//   out[:, 136:696) = max(x[i]+x[j]+x[k] - 2, 0)  i<j<k  (560)
// N = 131072 rows, 696 out cols (174 float4). Store-BW bound.
//
// Tile = 32 consecutive rows = 89,088B contiguous in global (128B-aligned
// span). Persistent CTA (1/SM, grid=152) loops over tiles with TWO smem
// buffers: compute tile into buf[it&1] while the previous tile's
// cp.async.bulk smem->global drains. wait_group 1 at iteration start frees
// the buffer written by group it-2. TMA engine streams full-line bursts
// continuously (R16 showed serial compute->drain->exit caps DRAM at 53%).

#define N_ROWS    131072
#define ROWS_PB   32
#define OUT_V4    174
#define TILE_V4   (ROWS_PB * OUT_V4)        // 5568 float4
#define TILE_BYTES (TILE_V4 * 16)           // 89,088 B
#define NTILES    (N_ROWS / ROWS_PB)        // 4096
#define BLOCK_T   256
#define GRID      152                       // GB300: 152 SMs, 1 CTA/SM

struct TabT {
    unsigned char k[696], a[696], b[696], c[696];
};

__host__ __device__ constexpr TabT make_tab() {
    TabT t{};
    int n = 0;
    for (int i = 0; i < 16; ++i) {
        t.k[n] = 1; t.a[n] = (unsigned char)i; t.b[n] = 0; t.c[n] = 0; ++n;
    }
    for (int i = 0; i < 16; ++i)
        for (int j = i + 1; j < 16; ++j) {
            t.k[n] = 2; t.a[n] = (unsigned char)i; t.b[n] = (unsigned char)j;
            t.c[n] = 0; ++n;
        }
    for (int i = 0; i < 16; ++i)
        for (int j = i + 1; j < 16; ++j)
            for (int l = j + 1; l < 16; ++l) {
                t.k[n] = 3; t.a[n] = (unsigned char)i; t.b[n] = (unsigned char)j;
                t.c[n] = (unsigned char)l; ++n;
            }
    return t;
}
__device__ constexpr TabT TAB = make_tab();

// Compute float4 columns [LO, HI) of this lane's row into shared.
// All TAB indices are literals after unroll -> pure FADD/FMNMX.
template <int LO, int HI>
__device__ __forceinline__ void compute_cols(const float xv[16],
                                             float4* __restrict__ shrow)
{
#pragma unroll
    for (int v4 = LO; v4 < HI; ++v4) {
        float r[4];
#pragma unroll
        for (int e = 0; e < 4; ++e) {
            const int col = v4 * 4 + e;
            const int K = TAB.k[col];
            const int A = TAB.a[col];
            const int B = TAB.b[col];
            const int C = TAB.c[col];
            if (K == 1)      r[e] = xv[A];
            else if (K == 2) r[e] = fmaxf(xv[A] + xv[B] - 1.0f, 0.0f);
            else             r[e] = fmaxf(xv[A] + (xv[B] + xv[C]) - 2.0f, 0.0f);
        }
        shrow[v4] = make_float4(r[0], r[1], r[2], r[3]);
    }
}

// Dispatch: 8 warps own ~equal column ranges (22*6 + 21*2 = 174).
__device__ __forceinline__ void compute_warp(int warp, const float xv[16],
                                             float4* __restrict__ shrow)
{
    switch (warp) {
        case 0: compute_cols<0,   22>(xv, shrow); break;
        case 1: compute_cols<22,  44>(xv, shrow); break;
        case 2: compute_cols<44,  66>(xv, shrow); break;
        case 3: compute_cols<66,  88>(xv, shrow); break;
        case 4: compute_cols<88, 110>(xv, shrow); break;
        case 5: compute_cols<110,132>(xv, shrow); break;
        case 6: compute_cols<132,153>(xv, shrow); break;
        default:compute_cols<153,174>(xv, shrow); break;
    }
}

__global__ void __launch_bounds__(BLOCK_T)
luk_kernel(const float4* __restrict__ x4, float4* __restrict__ out4)
{
    extern __shared__ float4 sh[];   // 2 x [ROWS_PB][OUT_V4], contiguous

    const int tid  = threadIdx.x;
    const int warp = tid >> 5;
    const int lane = tid & 31;

    int it = 0;
    for (int t = blockIdx.x; t < NTILES; t += GRID, ++it) {
        float4* __restrict__ buf = sh + (it & 1) * TILE_V4;

        // Free the buffer written by bulk group it-2 (≤1 group outstanding).
        if (it >= 2 && tid == 0)
            asm volatile("cp.async.bulk.wait_group 1;" ::: "memory");
        __syncthreads();

        // Load this lane's row of tile t (all 8 warps load the same 32 rows;
        // redundant loads hit L1).
        const long long myRow = (long long)t * ROWS_PB + lane;
        float xv[16];
        {
            const float4 v0 = x4[myRow * 4 + 0];
            const float4 v1 = x4[myRow * 4 + 1];
            const float4 v2 = x4[myRow * 4 + 2];
            const float4 v3 = x4[myRow * 4 + 3];
            xv[0]=v0.x;  xv[1]=v0.y;  xv[2]=v0.z;  xv[3]=v0.w;
            xv[4]=v1.x;  xv[5]=v1.y;  xv[6]=v1.z;  xv[7]=v1.w;
            xv[8]=v2.x;  xv[9]=v2.y;  xv[10]=v2.z; xv[11]=v2.w;
            xv[12]=v3.x; xv[13]=v3.y; xv[14]=v3.z; xv[15]=v3.w;
        }

        // Compute phase: lane = row; each warp owns a column range.
        compute_warp(warp, xv, buf + lane * OUT_V4);
        __syncthreads();

        // Issue async bulk store of the whole tile; no wait here.
        if (tid == 0) {
            asm volatile("fence.proxy.async.shared::cta;" ::: "memory");
            uint32_t saddr;
            asm("{ .reg .u64 tt; cvta.to.shared.u64 tt, %1; cvt.u32.u64 %0, tt; }"
                : "=r"(saddr) : "l"(buf));
            const float4* gdst = out4 + (long long)t * TILE_V4;
            asm volatile(
                "cp.async.bulk.global.shared::cta.bulk_group [%0], [%1], %2;"
                :: "l"(gdst), "r"(saddr), "r"((unsigned)TILE_BYTES) : "memory");
            asm volatile("cp.async.bulk.commit_group;" ::: "memory");
        }
    }

    // Final drain before exit.
    if (tid == 0)
        asm volatile("cp.async.bulk.wait_group 0;" ::: "memory");
}

extern "C" void kernel_launch(void* const* d_in, const int* in_sizes, int n_in,
                              void* d_out, int out_size)
{
    const float4* x4 = (const float4*)d_in[0];
    float4* out4 = (float4*)d_out;
    (void)in_sizes; (void)n_in; (void)out_size;

    cudaFuncSetAttribute(luk_kernel,
                         cudaFuncAttributeMaxDynamicSharedMemorySize,
                         2 * TILE_BYTES);

    luk_kernel<<<GRID, BLOCK_T, 2 * TILE_BYTES>>>(x4, out4);
}